// round 9
// baseline (speedup 1.0000x reference)
#include <cuda_runtime.h>
#include <cstdint>

#define D      1024
#define BS     80
#define NBATCH 16
#define STEPN  5
#define ALPHA  0.01f
#define NBLK   128
#define NTHR   512

#define WSTRD  1032                  // W smem row stride (floats), conflict-free
#define WFL    (16 * WSTRD)          // 16512 floats (64.5 KB)
#define QCH_FL (40 * 128)            // 5120 floats per q chunk stage
#define NSTAGE 4
#define DYN_FL (WFL + NSTAGE * QCH_FL)   // 36992 floats (~144.5 KB)
#define STGS   646                   // epilogue staging stride (floats)

// ---- global scratch (no device alloc allowed) ----
__device__ __align__(16) float g_qt[8 * 80 * 128];   // chunk-major q, swizzled
__device__ __align__(16) float g_y[BS * D];
__device__ __align__(16) float g_csum[2][D];
__device__ __align__(16) float g_csq[2][D];
// hierarchical barrier counters: 8 groups, padded 128B apart
__device__ unsigned g_grpA[8 * 32];
__device__ unsigned g_grpB[8 * 32];
__device__ unsigned g_grpD[8 * 32];

// ---- packed fp32x2 helpers ----
__device__ __forceinline__ void ffma2(unsigned long long& acc,
                                      unsigned long long a,
                                      unsigned long long b) {
    asm("fma.rn.f32x2 %0, %1, %2, %0;" : "+l"(acc) : "l"(a), "l"(b));
}
__device__ __forceinline__ float2 fold2f(unsigned long long v) {
    float lo, hi;
    asm("mov.b64 {%0, %1}, %2;" : "=f"(lo), "=f"(hi) : "l"(v));
    return make_float2(lo, hi);
}

// ---- mbarrier + bulk-copy helpers ----
__device__ __forceinline__ uint32_t s2u(const void* p) {
    return (uint32_t)__cvta_generic_to_shared(p);
}
__device__ __forceinline__ void mbar_init(uint32_t a, uint32_t cnt) {
    asm volatile("mbarrier.init.shared.b64 [%0], %1;" :: "r"(a), "r"(cnt) : "memory");
}
__device__ __forceinline__ void mbar_expect(uint32_t a, uint32_t bytes) {
    asm volatile("mbarrier.arrive.expect_tx.shared.b64 _, [%0], %1;"
                 :: "r"(a), "r"(bytes) : "memory");
}
__device__ __forceinline__ void bulk_g2s(uint32_t dst, const void* src,
                                         uint32_t bytes, uint32_t mbar) {
    asm volatile("cp.async.bulk.shared::cta.global.mbarrier::complete_tx::bytes "
                 "[%0], [%1], %2, [%3];"
                 :: "r"(dst), "l"(src), "r"(bytes), "r"(mbar) : "memory");
}
__device__ __forceinline__ void mbar_wait(uint32_t a, uint32_t parity) {
    asm volatile(
        "{\n\t"
        ".reg .pred P1;\n\t"
        "WAIT_LOOP_%=:\n\t"
        "mbarrier.try_wait.parity.acquire.cta.shared::cta.b64 P1, [%0], %1, 0x989680;\n\t"
        "@P1 bra.uni WAIT_DONE_%=;\n\t"
        "bra.uni WAIT_LOOP_%=;\n\t"
        "WAIT_DONE_%=:\n\t"
        "}"
        :: "r"(a), "r"(parity) : "memory");
}

// ---- hierarchical software grid barrier (single-wave grid) ----
__device__ __forceinline__ void gridbar_h(unsigned* grp, int bid) {
    __syncthreads();
    if (threadIdx.x == 0) {
        __threadfence();
        atomicAdd(&grp[(bid & 7) * 32], 1u);
#pragma unroll
        for (int g = 0; g < 8; g++)
            while (*(volatile unsigned*)&grp[g * 32] < 16u) { }
        __threadfence();
    }
    __syncthreads();
}

__global__ void __launch_bounds__(NTHR, 1)
fused_kernel(const float* __restrict__ x, const float* __restrict__ W,
             const float* __restrict__ bias, const float* __restrict__ gamma,
             const float* __restrict__ beta, float* __restrict__ out) {
    extern __shared__ __align__(16) float dynsm[];
    float* smW  = dynsm;          // [16][WSTRD]
    float* qstg = dynsm + WFL;    // NSTAGE x [40][128]

    __shared__ __align__(8) unsigned long long mbar[NSTAGE + 1]; // [0..3]=q, [4]=W
    __shared__ float ys[40 * 16];
    __shared__ float sred[STEPN][16];
    __shared__ float sd[STEPN];
    __shared__ float s_r[8];
    __shared__ float s_tot;

    const int tid = threadIdx.x;
    const int bid = blockIdx.x;
    const int rh  = bid >> 6;
    const int r0  = rh * 40;
    const int ct  = bid & 63;
    const int c0  = ct * 16;

    // ---- init mbarriers + issue full W tile copy (hidden under phase 1) ----
    if (tid == 0) {
#pragma unroll
        for (int i = 0; i < NSTAGE + 1; i++) mbar_init(s2u(&mbar[i]), 1);
        asm volatile("fence.proxy.async.shared::cta;" ::: "memory");
        uint32_t mw = s2u(&mbar[NSTAGE]);
        mbar_expect(mw, 16 * D * 4);
#pragma unroll
        for (int c = 0; c < 16; c++)
            bulk_g2s(s2u(smW + c * WSTRD), W + (c0 + c) * D, D * 4, mw);
    }

    // ---- phase 1: q rows (blocks 0..79), chunk-major swizzled store ----
    if (bid < BS) {
        const int n = bid;
        const int b = n % NBATCH;
        const int s = n / NBATCH;
        const int rb = b * STEPN;
        const int rot = (n & 7) << 2;

        float pd[STEPN] = {0.f, 0.f, 0.f, 0.f, 0.f};
        const float* xn = x + n * D;
        for (int j = tid; j < D; j += NTHR) {
            float v = xn[j];
#pragma unroll
            for (int t = 0; t < STEPN; t++)
                pd[t] += x[(rb + t) * D + j] * v;
        }
#pragma unroll
        for (int t = 0; t < STEPN; t++) {
            float v = pd[t];
#pragma unroll
            for (int o = 16; o > 0; o >>= 1)
                v += __shfl_down_sync(0xffffffffu, v, o);
            if ((tid & 31) == 0) sred[t][tid >> 5] = v;
        }
        __syncthreads();
        if (tid < STEPN) {
            float v = 0.f;
#pragma unroll
            for (int w = 0; w < 16; w++) v += sred[tid][w];
            sd[tid] = ALPHA * v;
        }
        __syncthreads();
        for (int i = tid; i < D; i += NTHR) {
            float g = 0.f;
            for (int t = 0; t <= s; t++) {
                float xv = x[(rb + t) * D + i];
                g = g * (1.f - ALPHA * xv * xv) + xv * sd[t];
            }
            g_qt[(i >> 7) * (80 * 128) + n * 128 + (((i & 127) + rot) & 127)] = g;
        }
    }

    gridbar_h(g_grpA, bid);

    // ================= phase 2: GEMM, q-only 4-deep pipeline ===============
    {
        const int w  = tid >> 5;
        const int lane = tid & 31;
        const int rg = lane >> 2;
        const int cg = lane & 3;
        const int w8 = w * 8;

        int qoff[5][2], wbase[4][2];
#pragma unroll
        for (int m = 0; m < 5; m++) {
            int row = rg * 5 + m;
            int rot = ((r0 + row) & 7) << 2;
#pragma unroll
            for (int qd = 0; qd < 2; qd++)
                qoff[m][qd] = row * 128 + ((w8 + qd * 4 + rot) & 127);
        }
#pragma unroll
        for (int cc = 0; cc < 4; cc++) {
            int rc = cc * 4 + cg;
#pragma unroll
            for (int qd = 0; qd < 2; qd++)
                wbase[cc][qd] = rc * WSTRD + w8 + qd * 4;
        }

        unsigned long long acc[5][4];
#pragma unroll
        for (int m = 0; m < 5; m++)
#pragma unroll
            for (int c = 0; c < 4; c++) acc[m][c] = 0ull;

        auto issue_q = [&](int ch) {
            const int buf = ch & 3;
            uint32_t mb = s2u(&mbar[buf]);
            mbar_expect(mb, QCH_FL * 4);
            bulk_g2s(s2u(qstg + buf * QCH_FL),
                     g_qt + ch * (80 * 128) + r0 * 128, QCH_FL * 4, mb);
        };

        if (tid == 0) { issue_q(0); issue_q(1); issue_q(2); issue_q(3); }

        mbar_wait(s2u(&mbar[NSTAGE]), 0);

        for (int ch = 0; ch < 8; ch++) {
            const int buf = ch & 3;
            mbar_wait(s2u(&mbar[buf]), (ch >> 2) & 1);

            const float* bq = qstg + buf * QCH_FL;
            const float* bw = smW + ch * 128;
#pragma unroll
            for (int qd = 0; qd < 2; qd++) {
                ulonglong2 qv[5];
#pragma unroll
                for (int m = 0; m < 5; m++)
                    qv[m] = *(const ulonglong2*)(bq + qoff[m][qd]);
#pragma unroll
                for (int cc = 0; cc < 4; cc++) {
                    ulonglong2 wv = *(const ulonglong2*)(bw + wbase[cc][qd]);
#pragma unroll
                    for (int m = 0; m < 5; m++) {
                        ffma2(acc[m][cc], qv[m].x, wv.x);
                        ffma2(acc[m][cc], qv[m].y, wv.y);
                    }
                }
            }
            __syncthreads();
            if (ch + NSTAGE < 8 && tid == 0) issue_q(ch + NSTAGE);
        }

        // stage folded partials (aliases smem, dead now); stride 646 ->
        // ww-loop reads in the reduce below are bank-conflict-free
        float* stg = dynsm;
        {
            float2* dst = (float2*)(stg + w * STGS + lane * 20);
#pragma unroll
            for (int m = 0; m < 5; m++) {
                float2 a = fold2f(acc[m][0]);
                float2 b = fold2f(acc[m][1]);
                float2 c = fold2f(acc[m][2]);
                float2 d = fold2f(acc[m][3]);
                dst[m * 2]     = make_float2(a.x + a.y, b.x + b.y);
                dst[m * 2 + 1] = make_float2(c.x + c.y, d.x + d.y);
            }
        }
        __syncthreads();

        // 16-way reduce + bias; write y
        for (int idx = tid; idx < 640; idx += NTHR) {
            const int row = idx >> 4, col = idx & 15;
            const int rg2 = row / 5, m = row - rg2 * 5;
            const int cg2 = col & 3, cc = col >> 2;
            const int off = (rg2 * 4 + cg2) * 20 + m * 4 + cc;
            float s = 0.f;
#pragma unroll
            for (int ww = 0; ww < 16; ww++)
                s += stg[ww * STGS + off];
            const float yv = s + bias[c0 + col];
            g_y[(r0 + row) * D + c0 + col] = yv;
            ys[row * 16 + col] = yv;
        }
        __syncthreads();

        // per-column partial stats over this block's 40 rows
        if (tid < 16) {
            float su = 0.f, sq = 0.f;
#pragma unroll
            for (int r = 0; r < 40; r++) {
                float v = ys[r * 16 + tid];
                su += v;
                sq += v * v;
            }
            g_csum[rh][c0 + tid] = su;
            g_csq[rh][c0 + tid]  = sq;
        }
    }

    gridbar_h(g_grpB, bid);

    // ================= phase 3: BN + relu + row L2-normalize =================
    {
        const bool act = (bid < BS) && (tid < 256);
        float z[4];
        float ss = 0.f;
        int k0 = tid * 4;
        if (act) {
            const int n = bid;
            float4 y4  = *(const float4*)(g_y + n * D + k0);
            float4 s04 = *(const float4*)(&g_csum[0][k0]);
            float4 s14 = *(const float4*)(&g_csum[1][k0]);
            float4 q04 = *(const float4*)(&g_csq[0][k0]);
            float4 q14 = *(const float4*)(&g_csq[1][k0]);
            float4 ga4 = *(const float4*)(gamma + k0);
            float4 be4 = *(const float4*)(beta + k0);

            const float inv = 1.f / (float)BS;
            float mu, var, rstd;
            mu = (s04.x + s14.x) * inv; var = (q04.x + q14.x) * inv - mu * mu;
            rstd = rsqrtf(var + 1e-5f);
            z[0] = fmaxf((y4.x - mu) * rstd * ga4.x + be4.x, 0.f);
            mu = (s04.y + s14.y) * inv; var = (q04.y + q14.y) * inv - mu * mu;
            rstd = rsqrtf(var + 1e-5f);
            z[1] = fmaxf((y4.y - mu) * rstd * ga4.y + be4.y, 0.f);
            mu = (s04.z + s14.z) * inv; var = (q04.z + q14.z) * inv - mu * mu;
            rstd = rsqrtf(var + 1e-5f);
            z[2] = fmaxf((y4.z - mu) * rstd * ga4.z + be4.z, 0.f);
            mu = (s04.w + s14.w) * inv; var = (q04.w + q14.w) * inv - mu * mu;
            rstd = rsqrtf(var + 1e-5f);
            z[3] = fmaxf((y4.w - mu) * rstd * ga4.w + be4.w, 0.f);

            ss = z[0] * z[0] + z[1] * z[1] + z[2] * z[2] + z[3] * z[3];
#pragma unroll
            for (int o = 16; o > 0; o >>= 1)
                ss += __shfl_down_sync(0xffffffffu, ss, o);
            if ((tid & 31) == 0) s_r[tid >> 5] = ss;
        }
        __syncthreads();
        if (act && tid == 0) {
            float t = 0.f;
#pragma unroll
            for (int w = 0; w < 8; w++) t += s_r[w];
            s_tot = 1.f / fmaxf(sqrtf(t), 1e-12f);
        }
        __syncthreads();
        if (act) {
            float sc = s_tot;
            float4 o4 = make_float4(z[0] * sc, z[1] * sc, z[2] * sc, z[3] * sc);
            *(float4*)(out + bid * D + k0) = o4;
        }
    }

    // ---- depart (off critical path) + replay-safe reset by block 0 ----
    __syncthreads();
    if (tid == 0) {
        __threadfence();
        atomicAdd(&g_grpD[(bid & 7) * 32], 1u);
        if (bid == 0) {
#pragma unroll
            for (int g = 0; g < 8; g++)
                while (*(volatile unsigned*)&g_grpD[g * 32] < 16u) { }
            __threadfence();
#pragma unroll
            for (int g = 0; g < 8; g++) {
                g_grpA[g * 32] = 0;
                g_grpB[g * 32] = 0;
                g_grpD[g * 32] = 0;
            }
            __threadfence();
        }
    }
}

extern "C" void kernel_launch(void* const* d_in, const int* in_sizes, int n_in,
                              void* d_out, int out_size) {
    (void)in_sizes; (void)n_in; (void)out_size;
    const float* x     = (const float*)d_in[0];
    const float* W     = (const float*)d_in[1];
    const float* bias  = (const float*)d_in[2];
    const float* gamma = (const float*)d_in[3];
    const float* beta  = (const float*)d_in[4];
    float* out = (float*)d_out;

    static int configured = 0;
    if (!configured) {
        cudaFuncSetAttribute(fused_kernel,
                             cudaFuncAttributeMaxDynamicSharedMemorySize,
                             DYN_FL * (int)sizeof(float));
        configured = 1;
    }
    fused_kernel<<<NBLK, NTHR, DYN_FL * sizeof(float)>>>(x, W, bias, gamma, beta, out);
}

// round 10
// speedup vs baseline: 1.3217x; 1.3217x over previous
#include <cuda_runtime.h>
#include <cstdint>

#define D      1024
#define BS     80
#define NBATCH 16
#define STEPN  5
#define ALPHA  0.01f
#define NBLK   128
#define NTHR   512

#define WSTRD  1032                  // W smem row stride (floats), conflict-free
#define WFL    (16 * WSTRD)          // 16512 floats (64.5 KB)
#define QCH_FL (40 * 128)            // 5120 floats per q chunk stage
#define NSTAGE 4
#define DYN_FL (WFL + NSTAGE * QCH_FL)   // 36992 floats (~144.5 KB)
#define STGS   646                   // epilogue staging stride (floats)

// mbar indices: 0..3 = q-full, 4 = W-full, 5..8 = q-empty
#define MB_W     4
#define MB_EMPTY 5

// ---- global scratch (no device alloc allowed) ----
__device__ __align__(16) float g_qt[8 * 80 * 128];   // chunk-major q, swizzled
__device__ __align__(16) float g_y[BS * D];
__device__ __align__(16) float g_csum[2][D];
__device__ __align__(16) float g_csq[2][D];
__device__ unsigned g_bar0, g_bar1, g_depart;

// ---- packed fp32x2 helpers ----
__device__ __forceinline__ void ffma2(unsigned long long& acc,
                                      unsigned long long a,
                                      unsigned long long b) {
    asm("fma.rn.f32x2 %0, %1, %2, %0;" : "+l"(acc) : "l"(a), "l"(b));
}
__device__ __forceinline__ float2 fold2f(unsigned long long v) {
    float lo, hi;
    asm("mov.b64 {%0, %1}, %2;" : "=f"(lo), "=f"(hi) : "l"(v));
    return make_float2(lo, hi);
}

// ---- mbarrier + bulk-copy helpers ----
__device__ __forceinline__ uint32_t s2u(const void* p) {
    return (uint32_t)__cvta_generic_to_shared(p);
}
__device__ __forceinline__ void mbar_init(uint32_t a, uint32_t cnt) {
    asm volatile("mbarrier.init.shared.b64 [%0], %1;" :: "r"(a), "r"(cnt) : "memory");
}
__device__ __forceinline__ void mbar_expect(uint32_t a, uint32_t bytes) {
    asm volatile("mbarrier.arrive.expect_tx.shared.b64 _, [%0], %1;"
                 :: "r"(a), "r"(bytes) : "memory");
}
__device__ __forceinline__ void mbar_arrive(uint32_t a) {
    asm volatile("mbarrier.arrive.release.cta.shared.b64 _, [%0];"
                 :: "r"(a) : "memory");
}
__device__ __forceinline__ void bulk_g2s(uint32_t dst, const void* src,
                                         uint32_t bytes, uint32_t mbar) {
    asm volatile("cp.async.bulk.shared::cta.global.mbarrier::complete_tx::bytes "
                 "[%0], [%1], %2, [%3];"
                 :: "r"(dst), "l"(src), "r"(bytes), "r"(mbar) : "memory");
}
__device__ __forceinline__ void mbar_wait(uint32_t a, uint32_t parity) {
    asm volatile(
        "{\n\t"
        ".reg .pred P1;\n\t"
        "WAIT_LOOP_%=:\n\t"
        "mbarrier.try_wait.parity.acquire.cta.shared::cta.b64 P1, [%0], %1, 0x989680;\n\t"
        "@P1 bra.uni WAIT_DONE_%=;\n\t"
        "bra.uni WAIT_LOOP_%=;\n\t"
        "WAIT_DONE_%=:\n\t"
        "}"
        :: "r"(a), "r"(parity) : "memory");
}

// ---- software grid barrier (single counter; single-wave grid) ----
__device__ __forceinline__ void gridbar(unsigned* cnt) {
    __syncthreads();
    if (threadIdx.x == 0) {
        __threadfence();
        atomicAdd(cnt, 1u);
        while (*(volatile unsigned*)cnt < NBLK) { }
        __threadfence();
    }
    __syncthreads();
}

__global__ void __launch_bounds__(NTHR, 1)
fused_kernel(const float* __restrict__ x, const float* __restrict__ W,
             const float* __restrict__ bias, const float* __restrict__ gamma,
             const float* __restrict__ beta, float* __restrict__ out) {
    extern __shared__ __align__(16) float dynsm[];
    float* smW  = dynsm;          // [16][WSTRD]
    float* qstg = dynsm + WFL;    // NSTAGE x [40][128]

    __shared__ __align__(8) unsigned long long mbar[9];
    __shared__ float ys[40 * 16];
    __shared__ float sred[STEPN][16];
    __shared__ float sd[STEPN];
    __shared__ float s_r[8];
    __shared__ float s_tot;

    const int tid = threadIdx.x;
    const int bid = blockIdx.x;
    const int rh  = bid >> 6;
    const int r0  = rh * 40;
    const int ct  = bid & 63;
    const int c0  = ct * 16;

    // ---- init mbarriers + issue full W tile copy (hidden under phase 1) ----
    if (tid == 0) {
#pragma unroll
        for (int i = 0; i < 5; i++) mbar_init(s2u(&mbar[i]), 1);
#pragma unroll
        for (int i = 0; i < 4; i++) mbar_init(s2u(&mbar[MB_EMPTY + i]), 16);
        asm volatile("fence.proxy.async.shared::cta;" ::: "memory");
        uint32_t mw = s2u(&mbar[MB_W]);
        mbar_expect(mw, 16 * D * 4);
#pragma unroll
        for (int c = 0; c < 16; c++)
            bulk_g2s(s2u(smW + c * WSTRD), W + (c0 + c) * D, D * 4, mw);
    }

    // ---- phase 1: q rows (blocks 0..79), chunk-major swizzled store ----
    if (bid < BS) {
        const int n = bid;
        const int b = n % NBATCH;
        const int s = n / NBATCH;
        const int rb = b * STEPN;
        const int rot = (n & 7) << 2;

        float pd[STEPN] = {0.f, 0.f, 0.f, 0.f, 0.f};
        const float* xn = x + n * D;
        for (int j = tid; j < D; j += NTHR) {
            float v = xn[j];
#pragma unroll
            for (int t = 0; t < STEPN; t++)
                pd[t] += x[(rb + t) * D + j] * v;
        }
#pragma unroll
        for (int t = 0; t < STEPN; t++) {
            float v = pd[t];
#pragma unroll
            for (int o = 16; o > 0; o >>= 1)
                v += __shfl_down_sync(0xffffffffu, v, o);
            if ((tid & 31) == 0) sred[t][tid >> 5] = v;
        }
        __syncthreads();
        if (tid < STEPN) {
            float v = 0.f;
#pragma unroll
            for (int w = 0; w < 16; w++) v += sred[tid][w];
            sd[tid] = ALPHA * v;
        }
        __syncthreads();
        for (int i = tid; i < D; i += NTHR) {
            float g = 0.f;
            for (int t = 0; t <= s; t++) {
                float xv = x[(rb + t) * D + i];
                g = g * (1.f - ALPHA * xv * xv) + xv * sd[t];
            }
            g_qt[(i >> 7) * (80 * 128) + n * 128 + (((i & 127) + rot) & 127)] = g;
        }
    } else {
        __syncthreads();
        __syncthreads();
    }

    gridbar(&g_bar0);

    // ================= phase 2: GEMM, q-only 4-deep pipeline ===============
    // consumer warps never block on each other: per-buffer empty mbarriers
    {
        const int w  = tid >> 5;
        const int lane = tid & 31;
        const int rg = lane >> 2;
        const int cg = lane & 3;
        const int w8 = w * 8;

        int qoff[5][2], wbase[4][2];
#pragma unroll
        for (int m = 0; m < 5; m++) {
            int row = rg * 5 + m;
            int rot = ((r0 + row) & 7) << 2;
#pragma unroll
            for (int qd = 0; qd < 2; qd++)
                qoff[m][qd] = row * 128 + ((w8 + qd * 4 + rot) & 127);
        }
#pragma unroll
        for (int cc = 0; cc < 4; cc++) {
            int rc = cc * 4 + cg;
#pragma unroll
            for (int qd = 0; qd < 2; qd++)
                wbase[cc][qd] = rc * WSTRD + w8 + qd * 4;
        }

        unsigned long long acc[5][4];
#pragma unroll
        for (int m = 0; m < 5; m++)
#pragma unroll
            for (int c = 0; c < 4; c++) acc[m][c] = 0ull;

        auto issue_q = [&](int ch) {
            const int buf = ch & 3;
            uint32_t mb = s2u(&mbar[buf]);
            mbar_expect(mb, QCH_FL * 4);
            bulk_g2s(s2u(qstg + buf * QCH_FL),
                     g_qt + ch * (80 * 128) + r0 * 128, QCH_FL * 4, mb);
        };

        if (tid == 0) { issue_q(0); issue_q(1); issue_q(2); issue_q(3); }

        mbar_wait(s2u(&mbar[MB_W]), 0);

        for (int ch = 0; ch < 8; ch++) {
            const int buf = ch & 3;
            mbar_wait(s2u(&mbar[buf]), (ch >> 2) & 1);

            const float* bq = qstg + buf * QCH_FL;
            const float* bw = smW + ch * 128;
#pragma unroll
            for (int qd = 0; qd < 2; qd++) {
                ulonglong2 qv[5];
#pragma unroll
                for (int m = 0; m < 5; m++)
                    qv[m] = *(const ulonglong2*)(bq + qoff[m][qd]);
#pragma unroll
                for (int cc = 0; cc < 4; cc++) {
                    ulonglong2 wv = *(const ulonglong2*)(bw + wbase[cc][qd]);
#pragma unroll
                    for (int m = 0; m < 5; m++) {
                        ffma2(acc[m][cc], qv[m].x, wv.x);
                        ffma2(acc[m][cc], qv[m].y, wv.y);
                    }
                }
            }
            // signal buffer free (non-blocking for consumers)
            if (ch < 4) {
                if (lane == 0) mbar_arrive(s2u(&mbar[MB_EMPTY + buf]));
                if (tid == 0) {
                    mbar_wait(s2u(&mbar[MB_EMPTY + buf]), 0);
                    issue_q(ch + NSTAGE);
                }
            }
        }

        __syncthreads();   // all warps done with mainloop (W area + q bufs)

        // stage folded partials (aliases W area, dead now); stride 646
        float* stg = dynsm;
        {
            float2* dst = (float2*)(stg + w * STGS + lane * 20);
#pragma unroll
            for (int m = 0; m < 5; m++) {
                float2 a = fold2f(acc[m][0]);
                float2 b = fold2f(acc[m][1]);
                float2 c = fold2f(acc[m][2]);
                float2 d = fold2f(acc[m][3]);
                dst[m * 2]     = make_float2(a.x + a.y, b.x + b.y);
                dst[m * 2 + 1] = make_float2(c.x + c.y, d.x + d.y);
            }
        }
        __syncthreads();

        // 16-way reduce + bias; write y
        for (int idx = tid; idx < 640; idx += NTHR) {
            const int row = idx >> 4, col = idx & 15;
            const int rg2 = row / 5, m = row - rg2 * 5;
            const int cg2 = col & 3, cc = col >> 2;
            const int off = (rg2 * 4 + cg2) * 20 + m * 4 + cc;
            float s = 0.f;
#pragma unroll
            for (int ww = 0; ww < 16; ww++)
                s += stg[ww * STGS + off];
            const float yv = s + bias[c0 + col];
            g_y[(r0 + row) * D + c0 + col] = yv;
            ys[row * 16 + col] = yv;
        }
        __syncthreads();

        // per-column partial stats over this block's 40 rows
        if (tid < 16) {
            float su = 0.f, sq = 0.f;
#pragma unroll
            for (int r = 0; r < 40; r++) {
                float v = ys[r * 16 + tid];
                su += v;
                sq += v * v;
            }
            g_csum[rh][c0 + tid] = su;
            g_csq[rh][c0 + tid]  = sq;
        }
    }

    gridbar(&g_bar1);

    // ================= phase 3: BN + relu + row L2-normalize =================
    {
        const bool act = (bid < BS) && (tid < 256);
        float z[4];
        float ss = 0.f;
        int k0 = tid * 4;
        if (act) {
            const int n = bid;
            float4 y4  = *(const float4*)(g_y + n * D + k0);
            float4 s04 = *(const float4*)(&g_csum[0][k0]);
            float4 s14 = *(const float4*)(&g_csum[1][k0]);
            float4 q04 = *(const float4*)(&g_csq[0][k0]);
            float4 q14 = *(const float4*)(&g_csq[1][k0]);
            float4 ga4 = *(const float4*)(gamma + k0);
            float4 be4 = *(const float4*)(beta + k0);

            const float inv = 1.f / (float)BS;
            float mu, var, rstd;
            mu = (s04.x + s14.x) * inv; var = (q04.x + q14.x) * inv - mu * mu;
            rstd = rsqrtf(var + 1e-5f);
            z[0] = fmaxf((y4.x - mu) * rstd * ga4.x + be4.x, 0.f);
            mu = (s04.y + s14.y) * inv; var = (q04.y + q14.y) * inv - mu * mu;
            rstd = rsqrtf(var + 1e-5f);
            z[1] = fmaxf((y4.y - mu) * rstd * ga4.y + be4.y, 0.f);
            mu = (s04.z + s14.z) * inv; var = (q04.z + q14.z) * inv - mu * mu;
            rstd = rsqrtf(var + 1e-5f);
            z[2] = fmaxf((y4.z - mu) * rstd * ga4.z + be4.z, 0.f);
            mu = (s04.w + s14.w) * inv; var = (q04.w + q14.w) * inv - mu * mu;
            rstd = rsqrtf(var + 1e-5f);
            z[3] = fmaxf((y4.w - mu) * rstd * ga4.w + be4.w, 0.f);

            ss = z[0] * z[0] + z[1] * z[1] + z[2] * z[2] + z[3] * z[3];
#pragma unroll
            for (int o = 16; o > 0; o >>= 1)
                ss += __shfl_down_sync(0xffffffffu, ss, o);
            if ((tid & 31) == 0) s_r[tid >> 5] = ss;
        }
        __syncthreads();
        if (act && tid == 0) {
            float t = 0.f;
#pragma unroll
            for (int w = 0; w < 8; w++) t += s_r[w];
            s_tot = 1.f / fmaxf(sqrtf(t), 1e-12f);
        }
        __syncthreads();
        if (act) {
            float sc = s_tot;
            float4 o4 = make_float4(z[0] * sc, z[1] * sc, z[2] * sc, z[3] * sc);
            *(float4*)(out + bid * D + k0) = o4;
        }
    }

    // ---- depart + replay-safe reset of barrier state ----
    if (threadIdx.x == 0) {
        __threadfence();
        unsigned old = atomicAdd(&g_depart, 1u);
        if (old == NBLK - 1) {
            g_bar0 = 0;
            g_bar1 = 0;
            __threadfence();
            g_depart = 0;
            __threadfence();
        }
    }
}

extern "C" void kernel_launch(void* const* d_in, const int* in_sizes, int n_in,
                              void* d_out, int out_size) {
    (void)in_sizes; (void)n_in; (void)out_size;
    const float* x     = (const float*)d_in[0];
    const float* W     = (const float*)d_in[1];
    const float* bias  = (const float*)d_in[2];
    const float* gamma = (const float*)d_in[3];
    const float* beta  = (const float*)d_in[4];
    float* out = (float*)d_out;

    static int configured = 0;
    if (!configured) {
        cudaFuncSetAttribute(fused_kernel,
                             cudaFuncAttributeMaxDynamicSharedMemorySize,
                             DYN_FL * (int)sizeof(float));
        configured = 1;
    }
    fused_kernel<<<NBLK, NTHR, DYN_FL * sizeof(float)>>>(x, W, bias, gamma, beta, out);
}

// round 11
// speedup vs baseline: 1.3239x; 1.0017x over previous
#include <cuda_runtime.h>
#include <cstdint>

#define D      1024
#define BS     80
#define NBATCH 16
#define STEPN  5
#define ALPHA  0.01f
#define NBLK   128
#define NTHR   512

#define WSTRD  1028                  // W smem row stride (floats): banks 0/4/8/12 -> conflict-free
#define WFL    (16 * WSTRD)          // 16448 floats
#define QCH_FL (40 * 128)            // 5120 floats per q chunk stage
#define DYN_FL (WFL + 8 * QCH_FL)    // 57408 floats = 229632 B
#define STGS   646                   // epilogue staging stride (floats)
#define MB_W   8                     // mbar index for W

// ---- global scratch (no device alloc allowed) ----
__device__ __align__(16) float g_qt[8 * 80 * 128];   // chunk-major q, swizzled
__device__ __align__(16) float g_y[BS * D];
__device__ __align__(16) float g_csum[2][D];
__device__ __align__(16) float g_csq[2][D];
__device__ unsigned g_rdy[2 * 32];   // half-row ready counters (padded)
__device__ unsigned g_bar1, g_depart;

// ---- packed fp32x2 helpers ----
__device__ __forceinline__ void ffma2(unsigned long long& acc,
                                      unsigned long long a,
                                      unsigned long long b) {
    asm("fma.rn.f32x2 %0, %1, %2, %0;" : "+l"(acc) : "l"(a), "l"(b));
}
__device__ __forceinline__ float2 fold2f(unsigned long long v) {
    float lo, hi;
    asm("mov.b64 {%0, %1}, %2;" : "=f"(lo), "=f"(hi) : "l"(v));
    return make_float2(lo, hi);
}

// ---- mbarrier + bulk-copy helpers ----
__device__ __forceinline__ uint32_t s2u(const void* p) {
    return (uint32_t)__cvta_generic_to_shared(p);
}
__device__ __forceinline__ void mbar_init(uint32_t a, uint32_t cnt) {
    asm volatile("mbarrier.init.shared.b64 [%0], %1;" :: "r"(a), "r"(cnt) : "memory");
}
__device__ __forceinline__ void mbar_expect(uint32_t a, uint32_t bytes) {
    asm volatile("mbarrier.arrive.expect_tx.shared.b64 _, [%0], %1;"
                 :: "r"(a), "r"(bytes) : "memory");
}
__device__ __forceinline__ void bulk_g2s(uint32_t dst, const void* src,
                                         uint32_t bytes, uint32_t mbar) {
    asm volatile("cp.async.bulk.shared::cta.global.mbarrier::complete_tx::bytes "
                 "[%0], [%1], %2, [%3];"
                 :: "r"(dst), "l"(src), "r"(bytes), "r"(mbar) : "memory");
}
__device__ __forceinline__ void mbar_wait(uint32_t a, uint32_t parity) {
    asm volatile(
        "{\n\t"
        ".reg .pred P1;\n\t"
        "WAIT_LOOP_%=:\n\t"
        "mbarrier.try_wait.parity.acquire.cta.shared::cta.b64 P1, [%0], %1, 0x989680;\n\t"
        "@P1 bra.uni WAIT_DONE_%=;\n\t"
        "bra.uni WAIT_LOOP_%=;\n\t"
        "WAIT_DONE_%=:\n\t"
        "}"
        :: "r"(a), "r"(parity) : "memory");
}

// ---- software grid barrier (single counter; single-wave grid) ----
__device__ __forceinline__ void gridbar(unsigned* cnt) {
    __syncthreads();
    if (threadIdx.x == 0) {
        __threadfence();
        atomicAdd(cnt, 1u);
        while (*(volatile unsigned*)cnt < NBLK) { }
        __threadfence();
    }
    __syncthreads();
}

__global__ void __launch_bounds__(NTHR, 1)
fused_kernel(const float* __restrict__ x, const float* __restrict__ W,
             const float* __restrict__ bias, const float* __restrict__ gamma,
             const float* __restrict__ beta, float* __restrict__ out) {
    extern __shared__ __align__(16) float dynsm[];
    float* smW  = dynsm;            // [16][WSTRD]
    float* qstg = dynsm + WFL;      // 8 x [40][128]

    // phase-1 scratch aliases q stages (unused until copies are issued,
    // which happens only after this block's phase-1 completes)
    float* sred = qstg;             // [5][16]
    float* sd   = qstg + 80;        // [5]
    // epilogue / phase-3 scratch aliases W + staging areas (dead post-mainloop)
    float* ysbuf = dynsm + 16 * STGS;        // 640 floats (within W area: 10336+640 < 16448)
    float* s_r   = dynsm + 16 * STGS + 640;  // 8
    float* s_tot = dynsm + 16 * STGS + 648;  // 1

    __shared__ __align__(8) unsigned long long mbar[9];  // 0..7 q-full, 8 W-full

    const int tid = threadIdx.x;
    const int bid = blockIdx.x;
    const int rh  = bid >> 6;
    const int r0  = rh * 40;
    const int ct  = bid & 63;
    const int c0  = ct * 16;

    // ---- init mbarriers + issue full W tile copy (hidden under phase 1) ----
    if (tid == 0) {
#pragma unroll
        for (int i = 0; i < 9; i++) mbar_init(s2u(&mbar[i]), 1);
        asm volatile("fence.proxy.async.shared::cta;" ::: "memory");
        uint32_t mw = s2u(&mbar[MB_W]);
        mbar_expect(mw, 16 * D * 4);
#pragma unroll
        for (int c = 0; c < 16; c++)
            bulk_g2s(s2u(smW + c * WSTRD), W + (c0 + c) * D, D * 4, mw);
    }
    __syncthreads();   // mbar init visible block-wide

    // ---- phase 1: q rows (blocks 0..79), chunk-major swizzled store ----
    if (bid < BS) {
        const int n = bid;
        const int b = n % NBATCH;
        const int s = n / NBATCH;
        const int rb = b * STEPN;
        const int rot = (n & 7) << 2;

        float pd[STEPN] = {0.f, 0.f, 0.f, 0.f, 0.f};
        const float* xn = x + n * D;
        for (int j = tid; j < D; j += NTHR) {
            float v = xn[j];
#pragma unroll
            for (int t = 0; t < STEPN; t++)
                pd[t] += x[(rb + t) * D + j] * v;
        }
#pragma unroll
        for (int t = 0; t < STEPN; t++) {
            float v = pd[t];
#pragma unroll
            for (int o = 16; o > 0; o >>= 1)
                v += __shfl_down_sync(0xffffffffu, v, o);
            if ((tid & 31) == 0) sred[t * 16 + (tid >> 5)] = v;
        }
        __syncthreads();
        if (tid < STEPN) {
            float v = 0.f;
#pragma unroll
            for (int w = 0; w < 16; w++) v += sred[tid * 16 + w];
            sd[tid] = ALPHA * v;
        }
        __syncthreads();
        for (int i = tid; i < D; i += NTHR) {
            float g = 0.f;
            for (int t = 0; t <= s; t++) {
                float xv = x[(rb + t) * D + i];
                g = g * (1.f - ALPHA * xv * xv) + xv * sd[t];
            }
            g_qt[(i >> 7) * (80 * 128) + n * 128 + (((i & 127) + rot) & 127)] = g;
        }
        __syncthreads();   // row fully published
        if (tid == 0) {
            __threadfence();
            atomicAdd(&g_rdy[(n >= 40) * 32], 1u);
        }
    }

    // ================= phase 2: GEMM, all-8-stage pipeline, no mainloop syncs
    {
        const int w  = tid >> 5;
        const int lane = tid & 31;
        const int rg = lane >> 2;
        const int cg = lane & 3;
        const int w8 = w * 8;

        int qoff[5][2], wbase[4][2];
#pragma unroll
        for (int m = 0; m < 5; m++) {
            int row = rg * 5 + m;
            int rot = ((r0 + row) & 7) << 2;
#pragma unroll
            for (int qd = 0; qd < 2; qd++)
                qoff[m][qd] = row * 128 + ((w8 + qd * 4 + rot) & 127);
        }
#pragma unroll
        for (int cc = 0; cc < 4; cc++) {
            int rc = cc * 4 + cg;
#pragma unroll
            for (int qd = 0; qd < 2; qd++)
                wbase[cc][qd] = rc * WSTRD + w8 + qd * 4;
        }

        unsigned long long acc[5][4];
#pragma unroll
        for (int m = 0; m < 5; m++)
#pragma unroll
            for (int c = 0; c < 4; c++) acc[m][c] = 0ull;

        // issuer: wait for this block's 40 rows, then fire all 8 chunk copies
        if (tid == 0) {
            while (*(volatile unsigned*)&g_rdy[rh * 32] < 40u) { }
            __threadfence();
#pragma unroll
            for (int ch = 0; ch < 8; ch++) {
                uint32_t mb = s2u(&mbar[ch]);
                mbar_expect(mb, QCH_FL * 4);
                bulk_g2s(s2u(qstg + ch * QCH_FL),
                         g_qt + ch * (80 * 128) + r0 * 128, QCH_FL * 4, mb);
            }
        }

        mbar_wait(s2u(&mbar[MB_W]), 0);

        for (int ch = 0; ch < 8; ch++) {
            mbar_wait(s2u(&mbar[ch]), 0);

            const float* bq = qstg + ch * QCH_FL;
            const float* bw = smW + ch * 128;
#pragma unroll
            for (int qd = 0; qd < 2; qd++) {
                ulonglong2 qv[5];
#pragma unroll
                for (int m = 0; m < 5; m++)
                    qv[m] = *(const ulonglong2*)(bq + qoff[m][qd]);
#pragma unroll
                for (int cc = 0; cc < 4; cc++) {
                    ulonglong2 wv = *(const ulonglong2*)(bw + wbase[cc][qd]);
#pragma unroll
                    for (int m = 0; m < 5; m++) {
                        ffma2(acc[m][cc], qv[m].x, wv.x);
                        ffma2(acc[m][cc], qv[m].y, wv.y);
                    }
                }
            }
        }

        __syncthreads();   // mainloop done; smem reusable

        // stage folded partials (aliases W area); stride 646 conflict-free
        float* stg = dynsm;
        {
            float2* dst = (float2*)(stg + w * STGS + lane * 20);
#pragma unroll
            for (int m = 0; m < 5; m++) {
                float2 a = fold2f(acc[m][0]);
                float2 b = fold2f(acc[m][1]);
                float2 c = fold2f(acc[m][2]);
                float2 d = fold2f(acc[m][3]);
                dst[m * 2]     = make_float2(a.x + a.y, b.x + b.y);
                dst[m * 2 + 1] = make_float2(c.x + c.y, d.x + d.y);
            }
        }
        __syncthreads();

        // 16-way reduce + bias; write y
        for (int idx = tid; idx < 640; idx += NTHR) {
            const int row = idx >> 4, col = idx & 15;
            const int rg2 = row / 5, m = row - rg2 * 5;
            const int cg2 = col & 3, cc = col >> 2;
            const int off = (rg2 * 4 + cg2) * 20 + m * 4 + cc;
            float s = 0.f;
#pragma unroll
            for (int ww = 0; ww < 16; ww++)
                s += stg[ww * STGS + off];
            const float yv = s + bias[c0 + col];
            g_y[(r0 + row) * D + c0 + col] = yv;
            ysbuf[row * 16 + col] = yv;
        }
        __syncthreads();

        // per-column partial stats over this block's 40 rows
        if (tid < 16) {
            float su = 0.f, sq = 0.f;
#pragma unroll
            for (int r = 0; r < 40; r++) {
                float v = ysbuf[r * 16 + tid];
                su += v;
                sq += v * v;
            }
            g_csum[rh][c0 + tid] = su;
            g_csq[rh][c0 + tid]  = sq;
        }
    }

    gridbar(&g_bar1);

    // ================= phase 3: BN + relu + row L2-normalize =================
    {
        const bool act = (bid < BS) && (tid < 256);
        float z[4];
        float ss = 0.f;
        int k0 = tid * 4;
        if (act) {
            const int n = bid;
            float4 y4  = *(const float4*)(g_y + n * D + k0);
            float4 s04 = *(const float4*)(&g_csum[0][k0]);
            float4 s14 = *(const float4*)(&g_csum[1][k0]);
            float4 q04 = *(const float4*)(&g_csq[0][k0]);
            float4 q14 = *(const float4*)(&g_csq[1][k0]);
            float4 ga4 = *(const float4*)(gamma + k0);
            float4 be4 = *(const float4*)(beta + k0);

            const float inv = 1.f / (float)BS;
            float mu, var, rstd;
            mu = (s04.x + s14.x) * inv; var = (q04.x + q14.x) * inv - mu * mu;
            rstd = rsqrtf(var + 1e-5f);
            z[0] = fmaxf((y4.x - mu) * rstd * ga4.x + be4.x, 0.f);
            mu = (s04.y + s14.y) * inv; var = (q04.y + q14.y) * inv - mu * mu;
            rstd = rsqrtf(var + 1e-5f);
            z[1] = fmaxf((y4.y - mu) * rstd * ga4.y + be4.y, 0.f);
            mu = (s04.z + s14.z) * inv; var = (q04.z + q14.z) * inv - mu * mu;
            rstd = rsqrtf(var + 1e-5f);
            z[2] = fmaxf((y4.z - mu) * rstd * ga4.z + be4.z, 0.f);
            mu = (s04.w + s14.w) * inv; var = (q04.w + q14.w) * inv - mu * mu;
            rstd = rsqrtf(var + 1e-5f);
            z[3] = fmaxf((y4.w - mu) * rstd * ga4.w + be4.w, 0.f);

            ss = z[0] * z[0] + z[1] * z[1] + z[2] * z[2] + z[3] * z[3];
#pragma unroll
            for (int o = 16; o > 0; o >>= 1)
                ss += __shfl_down_sync(0xffffffffu, ss, o);
            if ((tid & 31) == 0) s_r[tid >> 5] = ss;
        }
        __syncthreads();
        if (act && tid == 0) {
            float t = 0.f;
#pragma unroll
            for (int w = 0; w < 8; w++) t += s_r[w];
            s_tot[0] = 1.f / fmaxf(sqrtf(t), 1e-12f);
        }
        __syncthreads();
        if (act) {
            float sc = s_tot[0];
            float4 o4 = make_float4(z[0] * sc, z[1] * sc, z[2] * sc, z[3] * sc);
            *(float4*)(out + bid * D + k0) = o4;
        }
    }

    // ---- depart + replay-safe reset of barrier state ----
    if (tid == 0) {
        __threadfence();
        unsigned old = atomicAdd(&g_depart, 1u);
        if (old == NBLK - 1) {
            g_bar1 = 0;
            g_rdy[0] = 0;
            g_rdy[32] = 0;
            __threadfence();
            g_depart = 0;
            __threadfence();
        }
    }
}

extern "C" void kernel_launch(void* const* d_in, const int* in_sizes, int n_in,
                              void* d_out, int out_size) {
    (void)in_sizes; (void)n_in; (void)out_size;
    const float* x     = (const float*)d_in[0];
    const float* W     = (const float*)d_in[1];
    const float* bias  = (const float*)d_in[2];
    const float* gamma = (const float*)d_in[3];
    const float* beta  = (const float*)d_in[4];
    float* out = (float*)d_out;

    static int configured = 0;
    if (!configured) {
        cudaFuncSetAttribute(fused_kernel,
                             cudaFuncAttributeMaxDynamicSharedMemorySize,
                             DYN_FL * (int)sizeof(float));
        configured = 1;
    }
    fused_kernel<<<NBLK, NTHR, DYN_FL * sizeof(float)>>>(x, W, bias, gamma, beta, out);
}